// round 1
// baseline (speedup 1.0000x reference)
#include <cuda_runtime.h>
#include <math.h>

#define BB   8
#define NN   2048
#define DD   256
#define EE   16
#define HH   8
#define CAPC 256
#define NTOK (BB*NN)

// ------------------------- device scratch (no allocs) -------------------------
__device__ int   d_idx1[NTOK];
__device__ int   d_idx2[NTOK];
__device__ float d_g1[NTOK];
__device__ float d_g2[NTOK];
__device__ float d_probsum[BB*EE];
__device__ int   d_count1[BB*EE];
__device__ int   d_slot_tok[EE*BB*CAPC];
__device__ float d_gates[EE*BB*DD];

// ------------------------- init -------------------------
__global__ void k_init() {
    int i = blockIdx.x * blockDim.x + threadIdx.x;
    if (i < BB*EE) { d_probsum[i] = 0.f; d_count1[i] = 0; }
    if (i < EE*BB*CAPC) d_slot_tok[i] = -1;
}

// ------------------------- gating: warp per token -------------------------
__global__ void k_gating(const float* __restrict__ x, const float* __restrict__ wg) {
    __shared__ float sprob[EE];
    __shared__ int   scnt[EE];
    int tid = threadIdx.x;
    if (tid < EE) { sprob[tid] = 0.f; scnt[tid] = 0; }
    __syncthreads();

    int warp = tid >> 5, lane = tid & 31;
    int token = blockIdx.x * 8 + warp;           // 8 tokens per block, same b
    const float* xr = x + (size_t)token * DD;

    float p[EE];
#pragma unroll
    for (int e = 0; e < EE; e++) p[e] = 0.f;
#pragma unroll
    for (int k = 0; k < 8; k++) {
        int d0 = lane + 32*k;
        float xv = xr[d0];
#pragma unroll
        for (int e = 0; e < EE; e++) p[e] += xv * wg[d0*EE + e];
    }
#pragma unroll
    for (int e = 0; e < EE; e++) {
#pragma unroll
        for (int off = 16; off > 0; off >>= 1)
            p[e] += __shfl_xor_sync(0xffffffffu, p[e], off);
    }
    // softmax over 16
    float mx = p[0];
#pragma unroll
    for (int e = 1; e < EE; e++) mx = fmaxf(mx, p[e]);
    float s = 0.f;
#pragma unroll
    for (int e = 0; e < EE; e++) { p[e] = expf(p[e] - mx); s += p[e]; }
    float inv = 1.f / s;
#pragma unroll
    for (int e = 0; e < EE; e++) p[e] *= inv;
    // top-1 (first max), top-2 (first max excluding i1)
    int i1 = 0; float g1v = p[0];
#pragma unroll
    for (int e = 1; e < EE; e++) if (p[e] > g1v) { g1v = p[e]; i1 = e; }
    int i2 = (i1 == 0) ? 1 : 0; float g2v = p[i2];
#pragma unroll
    for (int e = 0; e < EE; e++)
        if (e != i1 && p[e] > g2v) { g2v = p[e]; i2 = e; }
    float denom = g1v + g2v + 1e-9f;

    if (lane == 0) {
        d_idx1[token] = i1; d_idx2[token] = i2;
        d_g1[token] = g1v / denom; d_g2[token] = g2v / denom;
        atomicAdd(&scnt[i1], 1);
    }
    if (lane < EE) atomicAdd(&sprob[lane], p[lane]);
    __syncthreads();
    if (tid < EE) {
        int b = (blockIdx.x * 8) / NN;
        atomicAdd(&d_probsum[b*EE + tid], sprob[tid]);
        atomicAdd(&d_count1[b*EE + tid], scnt[tid]);
    }
}

// ------------------------- capacity positions: block per (b,e) -------------------------
__global__ void k_positions() {
    int b = blockIdx.x / EE;
    int e = blockIdx.x % EE;
    int tid = threadIdx.x;                        // 256 threads
    int lane = tid & 31, warp = tid >> 5;
    const int TPT = NN / 256;                     // 8 tokens/thread, contiguous
    int t0 = tid * TPT;

    __shared__ int wsum[9];
    __shared__ int s_base;

    for (int pass = 0; pass < 2; pass++) {
        const int* idx = (pass == 0) ? d_idx1 : d_idx2;
        int match[TPT];
        int cnt = 0;
#pragma unroll
        for (int k = 0; k < TPT; k++) {
            match[k] = (idx[b*NN + t0 + k] == e);
            cnt += match[k];
        }
        // warp inclusive scan
        int incl = cnt;
#pragma unroll
        for (int off = 1; off < 32; off <<= 1) {
            int v = __shfl_up_sync(0xffffffffu, incl, off);
            if (lane >= off) incl += v;
        }
        int excl = incl - cnt;
        if (lane == 31) wsum[warp] = incl;
        __syncthreads();
        if (tid == 0) {
            int run = 0;
            for (int w = 0; w < 8; w++) { int t = wsum[w]; wsum[w] = run; run += t; }
            wsum[8] = run;
            if (pass == 0) s_base = (run < CAPC) ? run : CAPC;   // m1_count (capped)
        }
        __syncthreads();
        int base = excl + wsum[warp] + ((pass == 1) ? s_base : 0);
#pragma unroll
        for (int k = 0; k < TPT; k++) {
            if (match[k]) {
                int n = t0 + k;
                if (base < CAPC) {
                    d_slot_tok[(e*BB + b)*CAPC + base] = n;
                } else {
                    if (pass == 0) d_g1[b*NN + n] = 0.f;
                    else           d_g2[b*NN + n] = 0.f;
                }
                base++;
            }
        }
        __syncthreads();
    }
}

// ------------------------- mixer: block per (e,b) -------------------------
__global__ void __launch_bounds__(256) k_mixer(
    const float* __restrict__ x, const float* __restrict__ audio,
    const float* __restrict__ Wq, const float* __restrict__ Wkv,
    const float* __restrict__ Wp, const float* __restrict__ bp)
{
    __shared__ int   stok[CAPC];
    __shared__ float sa[DD];
    __shared__ float sq[DD];
    __shared__ float sU[HH][DD];
    __shared__ float sAtt[HH][CAPC];
    __shared__ float sY[HH][DD];
    __shared__ float sO[DD];

    int e = blockIdx.x / BB;
    int b = blockIdx.x % BB;
    int tid = threadIdx.x, lane = tid & 31, warp = tid >> 5;

    stok[tid] = d_slot_tok[(e*BB + b)*CAPC + tid];
    sa[tid] = audio[b*DD + tid];
    __syncthreads();

    // q[j] = sum_d audio[d] * Wq[e][d][j]   (coalesced over j)
    const float* Wqe = Wq + (size_t)e*DD*DD;
    {
        float acc = 0.f;
        for (int d = 0; d < DD; d++) acc += sa[d] * Wqe[d*DD + tid];
        sq[tid] = acc;
    }
    __syncthreads();

    // U[h][d] = sum_t Wkv[e][d][h*32+t] * q[h*32+t]; warp w handles head w
    const float* Wkve = Wkv + (size_t)e*DD*2*DD;
    {
        float qv = sq[warp*32 + lane];
        for (int d = 0; d < DD; d++) {
            float v = Wkve[(size_t)d*512 + warp*32 + lane] * qv;
#pragma unroll
            for (int off = 16; off > 0; off >>= 1)
                v += __shfl_xor_sync(0xffffffffu, v, off);
            if (lane == 0) sU[warp][d] = v;
        }
    }
    __syncthreads();

    // logits[h][c] = scale * Xe[c] . U[h];  warp w handles slots [w*32, w*32+32)
    const float scale = 0.17677669529663687f;   // 32^-0.5
    for (int ci = 0; ci < 32; ci++) {
        int c = warp*32 + ci;
        int tok = stok[c];
        float part[HH];
        if (tok >= 0) {
            const float* xr = x + ((size_t)b*NN + tok)*DD;
            float xv[8];
#pragma unroll
            for (int k = 0; k < 8; k++) xv[k] = xr[lane + 32*k];
#pragma unroll
            for (int h = 0; h < HH; h++) {
                float s2 = 0.f;
#pragma unroll
                for (int k = 0; k < 8; k++) s2 += xv[k] * sU[h][lane + 32*k];
                part[h] = s2;
            }
        } else {
#pragma unroll
            for (int h = 0; h < HH; h++) part[h] = 0.f;
        }
#pragma unroll
        for (int h = 0; h < HH; h++) {
            float v = part[h];
#pragma unroll
            for (int off = 16; off > 0; off >>= 1)
                v += __shfl_xor_sync(0xffffffffu, v, off);
            if (lane == 0) sAtt[h][c] = (tok >= 0) ? v * scale : 0.f;
        }
    }
    __syncthreads();

    // softmax over 256 slots per head; warp w = head w (empty slots contribute exp(0-mx))
    {
        int h = warp;
        float vals[8];
        float mx = -1e30f;
#pragma unroll
        for (int k = 0; k < 8; k++) { vals[k] = sAtt[h][lane + 32*k]; mx = fmaxf(mx, vals[k]); }
#pragma unroll
        for (int off = 16; off > 0; off >>= 1)
            mx = fmaxf(mx, __shfl_xor_sync(0xffffffffu, mx, off));
        float s = 0.f;
#pragma unroll
        for (int k = 0; k < 8; k++) { vals[k] = expf(vals[k] - mx); s += vals[k]; }
#pragma unroll
        for (int off = 16; off > 0; off >>= 1)
            s += __shfl_xor_sync(0xffffffffu, s, off);
        float inv = 1.f / s;
#pragma unroll
        for (int k = 0; k < 8; k++) sAtt[h][lane + 32*k] = vals[k] * inv;
    }
    __syncthreads();

    // y[h][d] = sum_c attn[h][c] * Xe[c][d]  (coalesced over d per c)
    {
        float yv[HH];
#pragma unroll
        for (int h = 0; h < HH; h++) yv[h] = 0.f;
        for (int c = 0; c < CAPC; c++) {
            int tok = stok[c];
            if (tok >= 0) {
                float xv = x[((size_t)b*NN + tok)*DD + tid];
#pragma unroll
                for (int h = 0; h < HH; h++) yv[h] += sAtt[h][c] * xv;
            }
        }
#pragma unroll
        for (int h = 0; h < HH; h++) sY[h][tid] = yv[h];
    }
    __syncthreads();

    // o[j] = sum_d y[h(j)][d] * Wkv_v[e][d][256 + j]  (coalesced over j)
    {
        int h = tid >> 5;
        float o = 0.f;
        for (int d = 0; d < DD; d++)
            o += sY[h][d] * Wkve[(size_t)d*512 + 256 + tid];
        sO[tid] = o;
    }
    __syncthreads();

    // gate[d] = sigmoid(sum_j o[j]*Wp[e][j][d] + bp[e][d])
    {
        const float* Wpe = Wp + (size_t)e*DD*DD;
        float g = bp[e*DD + tid];
        for (int j = 0; j < DD; j++) g += sO[j] * Wpe[j*DD + tid];
        d_gates[(e*BB + b)*DD + tid] = 1.f / (1.f + expf(-g));
    }
}

// ------------------------- combine -------------------------
__global__ void k_combine(const float* __restrict__ x, float* __restrict__ out) {
    int token = blockIdx.x;
    int tid = threadIdx.x;
    int b = token / NN;
    int i1 = d_idx1[token], i2 = d_idx2[token];
    float w1 = d_g1[token], w2 = d_g2[token];
    float gv = w1 * d_gates[(i1*BB + b)*DD + tid]
             + w2 * d_gates[(i2*BB + b)*DD + tid];
    out[(size_t)token*DD + tid] = x[(size_t)token*DD + tid] * gv;
}

// ------------------------- loss -------------------------
__global__ void k_loss(float* __restrict__ out, int out_size) {
    __shared__ float red[128];
    int i = threadIdx.x;
    float v = d_probsum[i] * (float)d_count1[i];
    red[i] = v;
    __syncthreads();
    for (int s = 64; s > 0; s >>= 1) {
        if (i < s) red[i] += red[i + s];
        __syncthreads();
    }
    if (i == 0 && out_size > BB*NN*DD) {
        // loss = mean_{b,e}(proxy*density) * E^2 * 0.01
        //      = sum(probsum*count) / (N*N*B*E) * E*E * 0.01
        float coef = (float)(EE*EE) * 0.01f / ((float)NN * (float)NN * (float)(BB*EE));
        out[BB*NN*DD] = red[0] * coef;
    }
}

// ------------------------- launch -------------------------
extern "C" void kernel_launch(void* const* d_in, const int* in_sizes, int n_in,
                              void* d_out, int out_size) {
    const float* x     = (const float*)d_in[0];
    const float* audio = (const float*)d_in[1];
    const float* wg    = (const float*)d_in[2];
    const float* Wq    = (const float*)d_in[3];
    const float* Wkv   = (const float*)d_in[4];
    const float* Wp    = (const float*)d_in[5];
    const float* bp    = (const float*)d_in[6];
    float* out = (float*)d_out;

    k_init<<<128, 256>>>();
    k_gating<<<NTOK/8, 256>>>(x, wg);
    k_positions<<<BB*EE, 256>>>();
    k_mixer<<<EE*BB, 256>>>(x, audio, Wq, Wkv, Wp, bp);
    k_combine<<<NTOK, 256>>>(x, out);
    k_loss<<<1, 128>>>(out, out_size);
}

// round 2
// speedup vs baseline: 2.7484x; 2.7484x over previous
#include <cuda_runtime.h>
#include <math.h>

#define BB   8
#define NN   2048
#define DD   256
#define EE   16
#define HH   8
#define CAPC 256
#define NTOK (BB*NN)

// ------------------------- device scratch (no allocs) -------------------------
__device__ int   d_idx1[NTOK];
__device__ int   d_idx2[NTOK];
__device__ float d_g1[NTOK];
__device__ float d_g2[NTOK];
__device__ float d_probsum[BB*EE];
__device__ int   d_count1[BB*EE];
__device__ int   d_slot_tok[EE*BB*CAPC];
__device__ float d_gates[EE*BB*DD];
__device__ float d_wgT[EE*DD];          // transposed gating weights [e][d]

// ------------------------- init (also transposes w_gating) -------------------------
__global__ void k_init(const float* __restrict__ wg) {
    int i = blockIdx.x * blockDim.x + threadIdx.x;
    if (i < BB*EE) { d_probsum[i] = 0.f; d_count1[i] = 0; }
    if (i < EE*BB*CAPC) d_slot_tok[i] = -1;
    if (i < EE*DD) {
        // i = d*EE + e (coalesced read); write transposed
        int d = i >> 4, e = i & 15;
        d_wgT[e*DD + d] = wg[i];
    }
}

// ------------------------- gating: warp per token -------------------------
__global__ void k_gating(const float* __restrict__ x) {
    __shared__ float sprob[EE];
    __shared__ int   scnt[EE];
    int tid = threadIdx.x;
    if (tid < EE) { sprob[tid] = 0.f; scnt[tid] = 0; }
    __syncthreads();

    int warp = tid >> 5, lane = tid & 31;
    int token = blockIdx.x * 8 + warp;           // 8 tokens per block, same b
    const float* xr = x + (size_t)token * DD;

    float p[EE];
#pragma unroll
    for (int e = 0; e < EE; e++) p[e] = 0.f;
#pragma unroll
    for (int k = 0; k < 8; k++) {
        int d0 = lane + 32*k;
        float xv = xr[d0];
#pragma unroll
        for (int e = 0; e < EE; e++) p[e] += xv * d_wgT[e*DD + d0];  // coalesced
    }
#pragma unroll
    for (int e = 0; e < EE; e++) {
#pragma unroll
        for (int off = 16; off > 0; off >>= 1)
            p[e] += __shfl_xor_sync(0xffffffffu, p[e], off);
    }
    // softmax over 16
    float mx = p[0];
#pragma unroll
    for (int e = 1; e < EE; e++) mx = fmaxf(mx, p[e]);
    float s = 0.f;
#pragma unroll
    for (int e = 0; e < EE; e++) { p[e] = expf(p[e] - mx); s += p[e]; }
    float inv = 1.f / s;
#pragma unroll
    for (int e = 0; e < EE; e++) p[e] *= inv;
    // top-1 (first max), top-2 (first max excluding i1)
    int i1 = 0; float g1v = p[0];
#pragma unroll
    for (int e = 1; e < EE; e++) if (p[e] > g1v) { g1v = p[e]; i1 = e; }
    int i2 = (i1 == 0) ? 1 : 0; float g2v = p[i2];
#pragma unroll
    for (int e = 0; e < EE; e++)
        if (e != i1 && p[e] > g2v) { g2v = p[e]; i2 = e; }
    float denom = g1v + g2v + 1e-9f;

    if (lane == 0) {
        d_idx1[token] = i1; d_idx2[token] = i2;
        d_g1[token] = g1v / denom; d_g2[token] = g2v / denom;
        atomicAdd(&scnt[i1], 1);
    }
    if (lane < EE) atomicAdd(&sprob[lane], p[lane]);
    __syncthreads();
    if (tid < EE) {
        int b = (blockIdx.x * 8) / NN;
        atomicAdd(&d_probsum[b*EE + tid], sprob[tid]);
        atomicAdd(&d_count1[b*EE + tid], scnt[tid]);
    }
}

// ------------------------- capacity positions: block per (b,e) -------------------------
__global__ void k_positions() {
    int b = blockIdx.x / EE;
    int e = blockIdx.x % EE;
    int tid = threadIdx.x;                        // 256 threads
    int lane = tid & 31, warp = tid >> 5;
    const int TPT = NN / 256;                     // 8 tokens/thread, contiguous
    int t0 = tid * TPT;

    __shared__ int wsum[9];
    __shared__ int s_base;

    for (int pass = 0; pass < 2; pass++) {
        const int* idx = (pass == 0) ? d_idx1 : d_idx2;
        int4 v0 = *(const int4*)(idx + b*NN + t0);
        int4 v1 = *(const int4*)(idx + b*NN + t0 + 4);
        int mtch[TPT];
        mtch[0] = (v0.x == e); mtch[1] = (v0.y == e); mtch[2] = (v0.z == e); mtch[3] = (v0.w == e);
        mtch[4] = (v1.x == e); mtch[5] = (v1.y == e); mtch[6] = (v1.z == e); mtch[7] = (v1.w == e);
        int cnt = 0;
#pragma unroll
        for (int k = 0; k < TPT; k++) cnt += mtch[k];
        // warp inclusive scan
        int incl = cnt;
#pragma unroll
        for (int off = 1; off < 32; off <<= 1) {
            int v = __shfl_up_sync(0xffffffffu, incl, off);
            if (lane >= off) incl += v;
        }
        int excl = incl - cnt;
        if (lane == 31) wsum[warp] = incl;
        __syncthreads();
        if (tid == 0) {
            int run = 0;
            for (int w = 0; w < 8; w++) { int t = wsum[w]; wsum[w] = run; run += t; }
            wsum[8] = run;
            if (pass == 0) s_base = (run < CAPC) ? run : CAPC;   // m1_count (capped)
        }
        __syncthreads();
        int base = excl + wsum[warp] + ((pass == 1) ? s_base : 0);
#pragma unroll
        for (int k = 0; k < TPT; k++) {
            if (mtch[k]) {
                int n = t0 + k;
                if (base < CAPC) {
                    d_slot_tok[(e*BB + b)*CAPC + base] = n;
                } else {
                    if (pass == 0) d_g1[b*NN + n] = 0.f;
                    else           d_g2[b*NN + n] = 0.f;
                }
                base++;
            }
        }
        __syncthreads();
    }
}

// ------------------------- mixer: block per (e,b), 1024 threads, 4-way split phases -----
__global__ void __launch_bounds__(1024, 1) k_mixer(
    const float* __restrict__ x, const float* __restrict__ audio,
    const float* __restrict__ Wq, const float* __restrict__ Wkv,
    const float* __restrict__ Wp, const float* __restrict__ bp)
{
    __shared__ int   stok[CAPC];
    __shared__ float sa[DD];
    __shared__ float sq[DD];
    __shared__ float sO[DD];
    __shared__ float sU[HH][DD];
    __shared__ float sAtt[HH][CAPC];
    __shared__ float sY[HH][DD];
    __shared__ float sRed[4][4][DD];   // 16 KB, multi-purpose reduction buffer

    int e = blockIdx.x / BB;
    int b = blockIdx.x % BB;
    int tid = threadIdx.x, lane = tid & 31, warp = tid >> 5;
    int g = tid >> 8, wtid = tid & 255;           // warp-group (0..3), id within group

    if (tid < CAPC) stok[tid] = d_slot_tok[(e*BB + b)*CAPC + tid];
    else if (tid < 2*CAPC) sa[tid - CAPC] = audio[b*DD + (tid - CAPC)];
    __syncthreads();

    // ---- q[j] = sum_d audio[d]*Wq[e][d][j], 4-way split over d ----
    const float* Wqe = Wq + (size_t)e*DD*DD;
    {
        float acc = 0.f;
        int d0 = g*64;
#pragma unroll 4
        for (int d = d0; d < d0 + 64; d++) acc += sa[d] * Wqe[d*DD + wtid];
        sRed[g][0][wtid] = acc;
    }
    __syncthreads();
    if (tid < DD)
        sq[tid] = sRed[0][0][tid] + sRed[1][0][tid] + sRed[2][0][tid] + sRed[3][0][tid];
    __syncthreads();

    // ---- U[h][d] = sum_t Wkv_k[e][d][h*32+t]*q[h*32+t]; warp (h, d-quarter) ----
    const float* Wkve = Wkv + (size_t)e*DD*2*DD;
    {
        int h = warp & 7;
        int dbase = (warp >> 3) * 64;
        float qv = sq[h*32 + lane];
#pragma unroll 4
        for (int d = dbase; d < dbase + 64; d++) {
            float v = Wkve[(size_t)d*512 + h*32 + lane] * qv;
#pragma unroll
            for (int off = 16; off > 0; off >>= 1)
                v += __shfl_xor_sync(0xffffffffu, v, off);
            if (lane == 0) sU[h][d] = v;
        }
    }
    __syncthreads();

    // ---- logits[h][c] = scale * Xe[c].U[h]; warp handles 8 slots ----
    const float scale = 0.17677669529663687f;   // 32^-0.5
#pragma unroll
    for (int ci = 0; ci < 8; ci++) {
        int c = warp*8 + ci;
        int tok = stok[c];
        float part[HH];
        if (tok >= 0) {
            const float* xr = x + ((size_t)b*NN + tok)*DD;
            float xv[8];
#pragma unroll
            for (int k = 0; k < 8; k++) xv[k] = xr[lane + 32*k];
#pragma unroll
            for (int h = 0; h < HH; h++) {
                float s2 = 0.f;
#pragma unroll
                for (int k = 0; k < 8; k++) s2 += xv[k] * sU[h][lane + 32*k];
                part[h] = s2;
            }
        } else {
#pragma unroll
            for (int h = 0; h < HH; h++) part[h] = 0.f;
        }
#pragma unroll
        for (int h = 0; h < HH; h++) {
            float v = part[h];
#pragma unroll
            for (int off = 16; off > 0; off >>= 1)
                v += __shfl_xor_sync(0xffffffffu, v, off);
            if (lane == 0) sAtt[h][c] = (tok >= 0) ? v * scale : 0.f;
        }
    }
    __syncthreads();

    // ---- softmax over 256 slots per head; warps 0..7 ----
    if (warp < HH) {
        int h = warp;
        float vals[8];
        float mx = -1e30f;
#pragma unroll
        for (int k = 0; k < 8; k++) { vals[k] = sAtt[h][lane + 32*k]; mx = fmaxf(mx, vals[k]); }
#pragma unroll
        for (int off = 16; off > 0; off >>= 1)
            mx = fmaxf(mx, __shfl_xor_sync(0xffffffffu, mx, off));
        float s = 0.f;
#pragma unroll
        for (int k = 0; k < 8; k++) { vals[k] = expf(vals[k] - mx); s += vals[k]; }
#pragma unroll
        for (int off = 16; off > 0; off >>= 1)
            s += __shfl_xor_sync(0xffffffffu, s, off);
        float inv = 1.f / s;
#pragma unroll
        for (int k = 0; k < 8; k++) sAtt[h][lane + 32*k] = vals[k] * inv;
    }
    __syncthreads();

    // ---- y[h][d] = sum_c attn[h][c]*Xe[c][d]; group g covers 64 slots ----
    {
        float yv[HH];
#pragma unroll
        for (int h = 0; h < HH; h++) yv[h] = 0.f;
        int c0 = g*64;
        for (int ci = 0; ci < 64; ci++) {
            int c = c0 + ci;
            int tok = stok[c];
            if (tok >= 0) {
                float xv = x[((size_t)b*NN + tok)*DD + wtid];
#pragma unroll
                for (int h = 0; h < HH; h++) yv[h] += sAtt[h][c] * xv;
            }
        }
        // reduce across 4 groups, two rounds of 4 heads
#pragma unroll
        for (int r = 0; r < 2; r++) {
            __syncthreads();
#pragma unroll
            for (int hh = 0; hh < 4; hh++) sRed[g][hh][wtid] = yv[r*4 + hh];
            __syncthreads();
            // thread (g, wtid) reduces head (r*4+g) at dim wtid
            sY[r*4 + g][wtid] = sRed[0][g][wtid] + sRed[1][g][wtid]
                              + sRed[2][g][wtid] + sRed[3][g][wtid];
        }
    }
    __syncthreads();

    // ---- o[j] = sum_d y[h(j)][d]*Wkv_v[e][d][256+j]; 4-way split over d ----
    {
        int h = wtid >> 5;
        float acc = 0.f;
        int d0 = g*64;
#pragma unroll 4
        for (int d = d0; d < d0 + 64; d++)
            acc += sY[h][d] * Wkve[(size_t)d*512 + 256 + wtid];
        sRed[g][0][wtid] = acc;
    }
    __syncthreads();
    if (tid < DD)
        sO[tid] = sRed[0][0][tid] + sRed[1][0][tid] + sRed[2][0][tid] + sRed[3][0][tid];
    __syncthreads();

    // ---- gate[d] = sigmoid(sum_j o[j]*Wp[e][j][d] + bp); 4-way split over j ----
    {
        const float* Wpe = Wp + (size_t)e*DD*DD;
        float acc = 0.f;
        int j0 = g*64;
#pragma unroll 4
        for (int j = j0; j < j0 + 64; j++) acc += sO[j] * Wpe[j*DD + wtid];
        sRed[g][1][wtid] = acc;
    }
    __syncthreads();
    if (tid < DD) {
        float gsum = sRed[0][1][tid] + sRed[1][1][tid] + sRed[2][1][tid] + sRed[3][1][tid]
                   + bp[e*DD + tid];
        d_gates[(e*BB + b)*DD + tid] = 1.f / (1.f + expf(-gsum));
    }
}

// ------------------------- combine -------------------------
__global__ void k_combine(const float* __restrict__ x, float* __restrict__ out) {
    int token = blockIdx.x;
    int tid = threadIdx.x;
    int b = token / NN;
    int i1 = d_idx1[token], i2 = d_idx2[token];
    float w1 = d_g1[token], w2 = d_g2[token];
    float gv = w1 * d_gates[(i1*BB + b)*DD + tid]
             + w2 * d_gates[(i2*BB + b)*DD + tid];
    out[(size_t)token*DD + tid] = x[(size_t)token*DD + tid] * gv;
}

// ------------------------- loss -------------------------
__global__ void k_loss(float* __restrict__ out, int out_size) {
    __shared__ float red[128];
    int i = threadIdx.x;
    red[i] = d_probsum[i] * (float)d_count1[i];
    __syncthreads();
    for (int s = 64; s > 0; s >>= 1) {
        if (i < s) red[i] += red[i + s];
        __syncthreads();
    }
    if (i == 0 && out_size > BB*NN*DD) {
        float coef = (float)(EE*EE) * 0.01f / ((float)NN * (float)NN * (float)(BB*EE));
        out[BB*NN*DD] = red[0] * coef;
    }
}

// ------------------------- launch -------------------------
extern "C" void kernel_launch(void* const* d_in, const int* in_sizes, int n_in,
                              void* d_out, int out_size) {
    const float* x     = (const float*)d_in[0];
    const float* audio = (const float*)d_in[1];
    const float* wg    = (const float*)d_in[2];
    const float* Wq    = (const float*)d_in[3];
    const float* Wkv   = (const float*)d_in[4];
    const float* Wp    = (const float*)d_in[5];
    const float* bp    = (const float*)d_in[6];
    float* out = (float*)d_out;

    k_init<<<128, 256>>>(wg);
    k_gating<<<NTOK/8, 256>>>(x);
    k_positions<<<BB*EE, 256>>>();
    k_mixer<<<EE*BB, 1024>>>(x, audio, Wq, Wkv, Wp, bp);
    k_combine<<<NTOK, 256>>>(x, out);
    k_loss<<<1, 128>>>(out, out_size);
}

// round 3
// speedup vs baseline: 2.9198x; 1.0624x over previous
#include <cuda_runtime.h>
#include <math.h>

#define BB   8
#define NN   2048
#define DD   256
#define EE   16
#define HH   8
#define CAPC 256
#define NTOK (BB*NN)
#define EB   (EE*BB)

// ------------------------- device scratch (no allocs) -------------------------
__device__ int   d_idx1[NTOK];
__device__ int   d_idx2[NTOK];
__device__ int   d_pos1[NTOK];          // capacity slot or -1
__device__ int   d_pos2[NTOK];
__device__ float d_g1[NTOK];
__device__ float d_g2[NTOK];
__device__ float d_probsum[BB*EE];
__device__ int   d_count1[BB*EE];
__device__ int   d_slot_tok[EB*CAPC];
__device__ float d_U[EB*HH*DD];         // per-(e,b) projected query-through-K
__device__ float d_logits[EB*HH*CAPC];  // logits then attention (in-place)
__device__ float d_y[EB*HH*DD];         // attn @ Xe partial sums
__device__ float d_gates[EB*DD];
__device__ float d_wgT[EE*DD];          // transposed gating weights [e][d]

// ------------------------- init -------------------------
__global__ void k_init(const float* __restrict__ wg) {
    int i = blockIdx.x * blockDim.x + threadIdx.x;
    if (i < BB*EE) { d_probsum[i] = 0.f; d_count1[i] = 0; }
    if (i < EB*CAPC) d_slot_tok[i] = -1;
    if (i < EB*HH*CAPC) d_logits[i] = 0.f;   // empty slots => logit 0
    if (i < EB*HH*DD)   d_y[i] = 0.f;
    if (i < EE*DD) {
        int d = i >> 4, e = i & 15;          // i = d*EE + e (coalesced read)
        d_wgT[e*DD + d] = wg[i];
    }
}

// ------------------------- gating: warp per token (float4) -------------------------
__global__ void k_gating(const float* __restrict__ x) {
    __shared__ float sprob[EE];
    __shared__ int   scnt[EE];
    int tid = threadIdx.x;
    if (tid < EE) { sprob[tid] = 0.f; scnt[tid] = 0; }
    __syncthreads();

    int warp = tid >> 5, lane = tid & 31;
    int token = blockIdx.x * 8 + warp;           // 8 tokens per block, same b
    const float4* xr4 = (const float4*)(x + (size_t)token * DD);
    float4 xa = xr4[lane], xb = xr4[lane + 32];

    float p[EE];
#pragma unroll
    for (int e = 0; e < EE; e++) {
        const float4* w4 = (const float4*)(d_wgT + e*DD);
        float4 wa = w4[lane], wb = w4[lane + 32];
        p[e] = xa.x*wa.x + xa.y*wa.y + xa.z*wa.z + xa.w*wa.w
             + xb.x*wb.x + xb.y*wb.y + xb.z*wb.z + xb.w*wb.w;
    }
#pragma unroll
    for (int e = 0; e < EE; e++) {
#pragma unroll
        for (int off = 16; off > 0; off >>= 1)
            p[e] += __shfl_xor_sync(0xffffffffu, p[e], off);
    }
    // softmax over 16
    float mx = p[0];
#pragma unroll
    for (int e = 1; e < EE; e++) mx = fmaxf(mx, p[e]);
    float s = 0.f;
#pragma unroll
    for (int e = 0; e < EE; e++) { p[e] = expf(p[e] - mx); s += p[e]; }
    float inv = 1.f / s;
#pragma unroll
    for (int e = 0; e < EE; e++) p[e] *= inv;
    // top-1 (first max), top-2 (first max excluding i1)
    int i1 = 0; float g1v = p[0];
#pragma unroll
    for (int e = 1; e < EE; e++) if (p[e] > g1v) { g1v = p[e]; i1 = e; }
    int i2 = (i1 == 0) ? 1 : 0; float g2v = p[i2];
#pragma unroll
    for (int e = 0; e < EE; e++)
        if (e != i1 && p[e] > g2v) { g2v = p[e]; i2 = e; }
    float denom = g1v + g2v + 1e-9f;

    if (lane == 0) {
        d_idx1[token] = i1; d_idx2[token] = i2;
        d_g1[token] = g1v / denom; d_g2[token] = g2v / denom;
        atomicAdd(&scnt[i1], 1);
    }
    if (lane < EE) atomicAdd(&sprob[lane], p[lane]);
    __syncthreads();
    if (tid < EE) {
        int b = (blockIdx.x * 8) / NN;
        atomicAdd(&d_probsum[b*EE + tid], sprob[tid]);
        atomicAdd(&d_count1[b*EE + tid], scnt[tid]);
    }
}

// ------------------------- capacity positions: block per (b,e) -------------------------
__global__ void k_positions() {
    int b = blockIdx.x / EE;
    int e = blockIdx.x % EE;
    int tid = threadIdx.x;                        // 256 threads
    int lane = tid & 31, warp = tid >> 5;
    const int TPT = NN / 256;                     // 8 tokens/thread
    int t0 = tid * TPT;

    __shared__ int wsum[9];
    __shared__ int s_base;

    for (int pass = 0; pass < 2; pass++) {
        const int* idx = (pass == 0) ? d_idx1 : d_idx2;
        int4 v0 = *(const int4*)(idx + b*NN + t0);
        int4 v1 = *(const int4*)(idx + b*NN + t0 + 4);
        int mtch[TPT];
        mtch[0] = (v0.x == e); mtch[1] = (v0.y == e); mtch[2] = (v0.z == e); mtch[3] = (v0.w == e);
        mtch[4] = (v1.x == e); mtch[5] = (v1.y == e); mtch[6] = (v1.z == e); mtch[7] = (v1.w == e);
        int cnt = 0;
#pragma unroll
        for (int k = 0; k < TPT; k++) cnt += mtch[k];
        int incl = cnt;
#pragma unroll
        for (int off = 1; off < 32; off <<= 1) {
            int v = __shfl_up_sync(0xffffffffu, incl, off);
            if (lane >= off) incl += v;
        }
        int excl = incl - cnt;
        if (lane == 31) wsum[warp] = incl;
        __syncthreads();
        if (tid == 0) {
            int run = 0;
            for (int w = 0; w < 8; w++) { int t = wsum[w]; wsum[w] = run; run += t; }
            wsum[8] = run;
            if (pass == 0) s_base = (run < CAPC) ? run : CAPC;
        }
        __syncthreads();
        int base = excl + wsum[warp] + ((pass == 1) ? s_base : 0);
#pragma unroll
        for (int k = 0; k < TPT; k++) {
            if (mtch[k]) {
                int n = t0 + k;
                if (base < CAPC) {
                    d_slot_tok[(e*BB + b)*CAPC + base] = n;
                    if (pass == 0) d_pos1[b*NN + n] = base;
                    else           d_pos2[b*NN + n] = base;
                } else {
                    if (pass == 0) { d_g1[b*NN + n] = 0.f; d_pos1[b*NN + n] = -1; }
                    else           { d_g2[b*NN + n] = 0.f; d_pos2[b*NN + n] = -1; }
                }
                base++;
            }
        }
        __syncthreads();
    }
}

// ------------------------- qU: block per (e,b), 1024 threads -------------------------
__global__ void __launch_bounds__(1024, 1) k_qU(
    const float* __restrict__ audio, const float* __restrict__ Wq,
    const float* __restrict__ Wkv)
{
    __shared__ float sa[DD];
    __shared__ float sq[DD];
    __shared__ float sRed[4][DD];

    int e = blockIdx.x / BB;
    int b = blockIdx.x % BB;
    int tid = threadIdx.x, lane = tid & 31, warp = tid >> 5;
    int g = tid >> 8, wtid = tid & 255;

    if (tid < DD) sa[tid] = audio[b*DD + tid];
    __syncthreads();

    // q[j] = sum_d audio[d]*Wq[e][d][j], 4-way split over d
    const float* Wqe = Wq + (size_t)e*DD*DD;
    {
        float acc = 0.f;
        int d0 = g*64;
#pragma unroll 4
        for (int d = d0; d < d0 + 64; d++) acc += sa[d] * Wqe[d*DD + wtid];
        sRed[g][wtid] = acc;
    }
    __syncthreads();
    if (tid < DD)
        sq[tid] = sRed[0][tid] + sRed[1][tid] + sRed[2][tid] + sRed[3][tid];
    __syncthreads();

    // U[h][d] = sum_t Wkv_k[e][d][h*32+t]*q[h*32+t]; warp = (h, d-quarter)
    const float* Wkve = Wkv + (size_t)e*DD*2*DD;
    {
        int h = warp & 7;
        int dbase = (warp >> 3) * 64;
        float qv = sq[h*32 + lane];
        float* Urow = d_U + ((size_t)blockIdx.x*HH + h)*DD;
#pragma unroll 4
        for (int d = dbase; d < dbase + 64; d++) {
            float v = Wkve[(size_t)d*512 + h*32 + lane] * qv;
#pragma unroll
            for (int off = 16; off > 0; off >>= 1)
                v += __shfl_xor_sync(0xffffffffu, v, off);
            if (lane == 0) Urow[d] = v;
        }
    }
}

// ------------------------- logits: token-centric, warp per token -------------------------
__global__ void k_logits(const float* __restrict__ x) {
    const float scale = 0.17677669529663687f;   // 32^-0.5
    int tid = threadIdx.x, warp = tid >> 5, lane = tid & 31;
    int token = blockIdx.x * 8 + warp;
    int b = token >> 11;                          // token / NN

    const float4* xr4 = (const float4*)(x + (size_t)token * DD);
    float4 xa = xr4[lane], xb = xr4[lane + 32];

#pragma unroll
    for (int pass = 0; pass < 2; pass++) {
        int e    = (pass == 0) ? d_idx1[token] : d_idx2[token];
        int slot = (pass == 0) ? d_pos1[token] : d_pos2[token];
        if (slot < 0) continue;
        int eb = e*BB + b;
        const float* U = d_U + (size_t)eb*HH*DD;
#pragma unroll
        for (int h = 0; h < HH; h++) {
            const float4* u4 = (const float4*)(U + h*DD);
            float4 ua = u4[lane], ub = u4[lane + 32];
            float s = xa.x*ua.x + xa.y*ua.y + xa.z*ua.z + xa.w*ua.w
                    + xb.x*ub.x + xb.y*ub.y + xb.z*ub.z + xb.w*ub.w;
#pragma unroll
            for (int off = 16; off > 0; off >>= 1)
                s += __shfl_xor_sync(0xffffffffu, s, off);
            if (lane == 0)
                d_logits[((size_t)eb*HH + h)*CAPC + slot] = s * scale;
        }
    }
}

// ------------------------- softmax: block per (e,b), warp per head -------------------------
__global__ void k_softmax() {
    int warp = threadIdx.x >> 5, lane = threadIdx.x & 31;
    float* row = d_logits + ((size_t)blockIdx.x*HH + warp)*CAPC;
    float vals[8];
    float mx = -1e30f;
#pragma unroll
    for (int k = 0; k < 8; k++) { vals[k] = row[lane + 32*k]; mx = fmaxf(mx, vals[k]); }
#pragma unroll
    for (int off = 16; off > 0; off >>= 1)
        mx = fmaxf(mx, __shfl_xor_sync(0xffffffffu, mx, off));
    float s = 0.f;
#pragma unroll
    for (int k = 0; k < 8; k++) { vals[k] = expf(vals[k] - mx); s += vals[k]; }
#pragma unroll
    for (int off = 16; off > 0; off >>= 1)
        s += __shfl_xor_sync(0xffffffffu, s, off);
    float inv = 1.f / s;
#pragma unroll
    for (int k = 0; k < 8; k++) row[lane + 32*k] = vals[k] * inv;
}

// ------------------------- y partials: block per (e,b,quarter) -------------------------
__global__ void __launch_bounds__(256) k_y(const float* __restrict__ x) {
    __shared__ float satt[HH][64];
    __shared__ int   stok[64];

    int eb  = blockIdx.x >> 2;
    int qtr = blockIdx.x & 3;
    int b   = eb & (BB-1);
    int tid = threadIdx.x;

    if (tid < 64) stok[tid] = d_slot_tok[eb*CAPC + qtr*64 + tid];
    for (int i = tid; i < HH*64; i += 256) {
        int h = i >> 6, c = i & 63;
        satt[h][c] = d_logits[((size_t)eb*HH + h)*CAPC + qtr*64 + c];
    }
    __syncthreads();

    float yv[HH];
#pragma unroll
    for (int h = 0; h < HH; h++) yv[h] = 0.f;
    for (int ci = 0; ci < 64; ci++) {
        int tok = stok[ci];
        if (tok >= 0) {
            float xv = x[((size_t)b*NN + tok)*DD + tid];
#pragma unroll
            for (int h = 0; h < HH; h++) yv[h] += satt[h][ci] * xv;
        }
    }
#pragma unroll
    for (int h = 0; h < HH; h++)
        atomicAdd(&d_y[((size_t)eb*HH + h)*DD + tid], yv[h]);
}

// ------------------------- o + gate: block per (e,b), 1024 threads -------------------------
__global__ void __launch_bounds__(1024, 1) k_og(
    const float* __restrict__ Wkv, const float* __restrict__ Wp,
    const float* __restrict__ bp)
{
    __shared__ float sY[HH][DD];
    __shared__ float sO[DD];
    __shared__ float sRed[4][DD];

    int e = blockIdx.x / BB;
    int tid = threadIdx.x;
    int g = tid >> 8, wtid = tid & 255;

    for (int i = tid; i < HH*DD; i += 1024)
        ((float*)sY)[i] = d_y[(size_t)blockIdx.x*HH*DD + i];
    __syncthreads();

    // o[j] = sum_d y[h(j)][d]*Wkv_v[e][d][256+j]; 4-way split over d
    const float* Wkve = Wkv + (size_t)e*DD*2*DD;
    {
        int h = wtid >> 5;
        float acc = 0.f;
        int d0 = g*64;
#pragma unroll 4
        for (int d = d0; d < d0 + 64; d++)
            acc += sY[h][d] * Wkve[(size_t)d*512 + 256 + wtid];
        sRed[g][wtid] = acc;
    }
    __syncthreads();
    if (tid < DD)
        sO[tid] = sRed[0][tid] + sRed[1][tid] + sRed[2][tid] + sRed[3][tid];
    __syncthreads();

    // gate[d] = sigmoid(sum_j o[j]*Wp[e][j][d] + bp); 4-way split over j
    {
        const float* Wpe = Wp + (size_t)e*DD*DD;
        float acc = 0.f;
        int j0 = g*64;
#pragma unroll 4
        for (int j = j0; j < j0 + 64; j++) acc += sO[j] * Wpe[j*DD + wtid];
        sRed[g][wtid] = acc;
    }
    __syncthreads();
    if (tid < DD) {
        float gsum = sRed[0][tid] + sRed[1][tid] + sRed[2][tid] + sRed[3][tid]
                   + bp[e*DD + tid];
        d_gates[(size_t)blockIdx.x*DD + tid] = 1.f / (1.f + expf(-gsum));
    }
}

// ------------------------- combine (float4, 4 tokens per block) -------------------------
__global__ void k_combine(const float* __restrict__ x, float* __restrict__ out) {
    int tid = threadIdx.x;
    int token = blockIdx.x*4 + (tid >> 6);
    int q = tid & 63;
    int b = token >> 11;
    int i1 = d_idx1[token], i2 = d_idx2[token];
    float w1 = d_g1[token], w2 = d_g2[token];
    float4 xv = ((const float4*)x)[(size_t)token*64 + q];
    float4 ga = ((const float4*)(d_gates + (i1*BB + b)*DD))[q];
    float4 gb = ((const float4*)(d_gates + (i2*BB + b)*DD))[q];
    float4 o;
    o.x = xv.x * (w1*ga.x + w2*gb.x);
    o.y = xv.y * (w1*ga.y + w2*gb.y);
    o.z = xv.z * (w1*ga.z + w2*gb.z);
    o.w = xv.w * (w1*ga.w + w2*gb.w);
    ((float4*)out)[(size_t)token*64 + q] = o;
}

// ------------------------- loss -------------------------
__global__ void k_loss(float* __restrict__ out, int out_size) {
    __shared__ float red[128];
    int i = threadIdx.x;
    red[i] = d_probsum[i] * (float)d_count1[i];
    __syncthreads();
    for (int s = 64; s > 0; s >>= 1) {
        if (i < s) red[i] += red[i + s];
        __syncthreads();
    }
    if (i == 0 && out_size > BB*NN*DD) {
        float coef = (float)(EE*EE) * 0.01f / ((float)NN * (float)NN * (float)(BB*EE));
        out[BB*NN*DD] = red[0] * coef;
    }
}

// ------------------------- launch -------------------------
extern "C" void kernel_launch(void* const* d_in, const int* in_sizes, int n_in,
                              void* d_out, int out_size) {
    const float* x     = (const float*)d_in[0];
    const float* audio = (const float*)d_in[1];
    const float* wg    = (const float*)d_in[2];
    const float* Wq    = (const float*)d_in[3];
    const float* Wkv   = (const float*)d_in[4];
    const float* Wp    = (const float*)d_in[5];
    const float* bp    = (const float*)d_in[6];
    float* out = (float*)d_out;

    k_init<<<1024, 256>>>(wg);
    k_qU<<<EB, 1024>>>(audio, Wq, Wkv);
    k_gating<<<NTOK/8, 256>>>(x);
    k_positions<<<BB*EE, 256>>>();
    k_logits<<<NTOK/8, 256>>>(x);
    k_softmax<<<EB, 256>>>();
    k_y<<<EB*4, 256>>>(x);
    k_og<<<EB, 1024>>>(Wkv, Wp, bp);
    k_combine<<<NTOK/4, 256>>>(x, out);
    k_loss<<<1, 128>>>(out, out_size);
}